// round 1
// baseline (speedup 1.0000x reference)
#include <cuda_runtime.h>
#include <cuda_bf16.h>
#include <math.h>

// Problem constants
#define Bq  16
#define Tq  1024
#define Dq  256
#define Cq  1024
#define Kq  9

// GEMM tiling
#define BM 128
#define BN 128
#define BKT 16
#define TM 8
#define TN 8
// 256 threads = 16x16

// Scratch (device globals: allocation-free)
__device__ float g_h[(size_t)Bq * Cq * Tq];      // mish(w1@x^T+b1)   [b][c][t]
__device__ float g_conv[(size_t)Bq * Cq * Tq];   // depthwise conv    [b][c][t]
__device__ float g_tmp[(size_t)Bq * Cq * Tq];    // mish(pointwise)   [b][o][t]
__device__ float g_inv_pnorm[Bq * Cq];           // 1/max(||p_w[:,o]||,eps)
__device__ float g_inv_dnorm[Bq * Kq];           // 1/max(||d_w[:,k]||,eps)

__device__ __forceinline__ float mishf(float x) {
    // x * tanh(softplus(x)); softplus stable for large x
    float sp = (x > 20.f) ? x : log1pf(__expf(x));
    return x * tanhf(sp);
}

// ---------------------------------------------------------------------------
// Weight-norm denominators
// ---------------------------------------------------------------------------
__global__ void dnorm_kernel(const float* __restrict__ d_w) {
    // grid = B*K blocks, 256 threads; reduce over c
    int bk = blockIdx.x;
    int b = bk / Kq, k = bk % Kq;
    float s = 0.f;
    for (int c = threadIdx.x; c < Cq; c += 256) {
        float v = d_w[((size_t)b * Cq + c) * Kq + k];
        s = fmaf(v, v, s);
    }
    __shared__ float red[256];
    red[threadIdx.x] = s;
    __syncthreads();
    for (int off = 128; off > 0; off >>= 1) {
        if (threadIdx.x < off) red[threadIdx.x] += red[threadIdx.x + off];
        __syncthreads();
    }
    if (threadIdx.x == 0)
        g_inv_dnorm[bk] = 1.f / fmaxf(sqrtf(red[0]), 1e-12f);
}

__global__ void pnorm_kernel(const float* __restrict__ p_w) {
    // grid = (B, 4), 256 threads; each thread owns one o, loops over c
    int b = blockIdx.x;
    int o = blockIdx.y * 256 + threadIdx.x;
    const float* base = p_w + (size_t)b * Cq * Cq + o;
    float s = 0.f;
    #pragma unroll 4
    for (int c = 0; c < Cq; ++c) {
        float v = base[(size_t)c * Cq];
        s = fmaf(v, v, s);
    }
    g_inv_pnorm[b * Cq + o] = 1.f / fmaxf(sqrtf(s), 1e-12f);
}

// ---------------------------------------------------------------------------
// GEMM1: h[b,c,t] = mish( sum_d w1[c,d] * x[b,t,d] + b1[c] )
// A = w1 [C,D] row-major (k contiguous), B = x[b] [T,D] (k contiguous)
// ---------------------------------------------------------------------------
__global__ __launch_bounds__(256) void gemm1_kernel(
    const float* __restrict__ x, const float* __restrict__ w1,
    const float* __restrict__ b1)
{
    int b  = blockIdx.z;
    int m0 = blockIdx.y * BM;   // c
    int n0 = blockIdx.x * BN;   // t
    __shared__ float As[BKT][BM];
    __shared__ float Bs[BKT][BN];
    const float* Ag = w1;
    const float* Bg = x + (size_t)b * Tq * Dq;

    int tid = threadIdx.x;
    int ty = tid >> 4, tx = tid & 15;
    int lr  = tid >> 2;        // 0..63
    int lk4 = (tid & 3) * 4;   // {0,4,8,12}

    float acc[TM][TN] = {};

    for (int k0 = 0; k0 < Dq; k0 += BKT) {
        #pragma unroll
        for (int p = 0; p < 2; ++p) {
            int m = lr + p * 64;
            float4 v = *(const float4*)(Ag + (size_t)(m0 + m) * Dq + k0 + lk4);
            As[lk4 + 0][m] = v.x; As[lk4 + 1][m] = v.y;
            As[lk4 + 2][m] = v.z; As[lk4 + 3][m] = v.w;
        }
        #pragma unroll
        for (int p = 0; p < 2; ++p) {
            int n = lr + p * 64;
            float4 v = *(const float4*)(Bg + (size_t)(n0 + n) * Dq + k0 + lk4);
            Bs[lk4 + 0][n] = v.x; Bs[lk4 + 1][n] = v.y;
            Bs[lk4 + 2][n] = v.z; Bs[lk4 + 3][n] = v.w;
        }
        __syncthreads();
        #pragma unroll
        for (int kk = 0; kk < BKT; ++kk) {
            float a[TM], bb[TN];
            #pragma unroll
            for (int i = 0; i < TM; ++i) a[i]  = As[kk][ty * TM + i];
            #pragma unroll
            for (int j = 0; j < TN; ++j) bb[j] = Bs[kk][tx * TN + j];
            #pragma unroll
            for (int i = 0; i < TM; ++i)
                #pragma unroll
                for (int j = 0; j < TN; ++j)
                    acc[i][j] = fmaf(a[i], bb[j], acc[i][j]);
        }
        __syncthreads();
    }
    #pragma unroll
    for (int i = 0; i < TM; ++i) {
        int m = m0 + ty * TM + i;
        float bias = b1[m];
        float* row = g_h + (size_t)b * Cq * Tq + (size_t)m * Tq + n0 + tx * TN;
        #pragma unroll
        for (int j = 0; j < TN; ++j)
            row[j] = mishf(acc[i][j] + bias);
    }
}

// ---------------------------------------------------------------------------
// Depthwise conv: g_conv[b,c,t] = d_b[b,c] + sum_k h[b,c,t+k-4] * dwn[b,c,k]
// dwn[b,c,k] = d_w[b,c,0,k] * inv_dnorm[b,k] * d_g[b,c]
// ---------------------------------------------------------------------------
__global__ __launch_bounds__(256) void conv_kernel(
    const float* __restrict__ d_w, const float* __restrict__ d_g,
    const float* __restrict__ d_b)
{
    int bc = blockIdx.x;
    int b = bc >> 10;
    int c = bc & 1023;
    __shared__ float s[Tq + 8];
    int tid = threadIdx.x;
    const float* hrow = g_h + (size_t)bc * Tq;
    for (int t = tid; t < Tq; t += 256) s[t + 4] = hrow[t];
    if (tid < 8) s[(tid < 4) ? tid : (Tq + tid)] = 0.f;
    __syncthreads();

    float w[Kq];
    float g = d_g[b * Cq + c];
    #pragma unroll
    for (int k = 0; k < Kq; ++k)
        w[k] = d_w[(size_t)bc * Kq + k] * g_inv_dnorm[b * Kq + k] * g;
    float bias = d_b[b * Cq + c];

    float* orow = g_conv + (size_t)bc * Tq;
    for (int t = tid; t < Tq; t += 256) {
        float acc = bias;
        #pragma unroll
        for (int k = 0; k < Kq; ++k)
            acc = fmaf(s[t + k], w[k], acc);
        orow[t] = acc;
    }
}

// ---------------------------------------------------------------------------
// GEMM2 (dominant): tmp[b,o,t] = mish( inv_pnorm[b,o] *
//          sum_c p_w[b,c,o]*p_g[b,c]*conv[b,c,t]  + p_b[b,o] )
// A column-major in m (p_w: [c][o], o contiguous), B row-major in n.
// ---------------------------------------------------------------------------
__global__ __launch_bounds__(256) void gemm2_kernel(
    const float* __restrict__ p_w, const float* __restrict__ p_g,
    const float* __restrict__ p_b)
{
    int b  = blockIdx.z;
    int m0 = blockIdx.y * BM;   // o
    int n0 = blockIdx.x * BN;   // t
    __shared__ float As[BKT][BM];
    __shared__ float Bs[BKT][BN];
    const float* Ag = p_w + (size_t)b * Cq * Cq;   // [c][o]
    const float* Bg = g_conv + (size_t)b * Cq * Tq; // [c][t]
    const float* pg = p_g + b * Cq;

    int tid = threadIdx.x;
    int ty = tid >> 4, tx = tid & 15;
    int lk  = tid >> 5;        // 0..7
    int lm4 = (tid & 31) * 4;  // 0..124

    float acc[TM][TN] = {};

    for (int k0 = 0; k0 < Cq; k0 += BKT) {
        #pragma unroll
        for (int p = 0; p < 2; ++p) {
            int k = lk + p * 8;
            float gsc = pg[k0 + k];
            float4 v = *(const float4*)(Ag + (size_t)(k0 + k) * Cq + m0 + lm4);
            v.x *= gsc; v.y *= gsc; v.z *= gsc; v.w *= gsc;
            *(float4*)&As[k][lm4] = v;
            float4 u = *(const float4*)(Bg + (size_t)(k0 + k) * Tq + n0 + lm4);
            *(float4*)&Bs[k][lm4] = u;
        }
        __syncthreads();
        #pragma unroll
        for (int kk = 0; kk < BKT; ++kk) {
            float a[TM], bb[TN];
            #pragma unroll
            for (int i = 0; i < TM; ++i) a[i]  = As[kk][ty * TM + i];
            #pragma unroll
            for (int j = 0; j < TN; ++j) bb[j] = Bs[kk][tx * TN + j];
            #pragma unroll
            for (int i = 0; i < TM; ++i)
                #pragma unroll
                for (int j = 0; j < TN; ++j)
                    acc[i][j] = fmaf(a[i], bb[j], acc[i][j]);
        }
        __syncthreads();
    }
    #pragma unroll
    for (int i = 0; i < TM; ++i) {
        int m = m0 + ty * TM + i;
        float s  = g_inv_pnorm[b * Cq + m];
        float pb = p_b[b * Cq + m];
        float* row = g_tmp + (size_t)b * Cq * Tq + (size_t)m * Tq + n0 + tx * TN;
        #pragma unroll
        for (int j = 0; j < TN; ++j)
            row[j] = mishf(acc[i][j] * s + pb);
    }
}

// ---------------------------------------------------------------------------
// GEMM3: out[b,t,d] = sum_c w2[d,c]*tmp[b,c,t] + b2[d] + x[b,t,d]
// A = w2 [D,C] row-major (k contiguous), B = tmp[b] [C,T] (n contiguous)
// Output column-major in m (d contiguous).
// ---------------------------------------------------------------------------
__global__ __launch_bounds__(256) void gemm3_kernel(
    const float* __restrict__ x, const float* __restrict__ w2,
    const float* __restrict__ b2, float* __restrict__ out)
{
    int b  = blockIdx.z;
    int m0 = blockIdx.y * BM;   // d
    int n0 = blockIdx.x * BN;   // t
    __shared__ float As[BKT][BM];
    __shared__ float Bs[BKT][BN];
    const float* Ag = w2;                          // [D][C]
    const float* Bg = g_tmp + (size_t)b * Cq * Tq; // [c][t]

    int tid = threadIdx.x;
    int ty = tid >> 4, tx = tid & 15;
    int lr  = tid >> 2;        // 0..63  (A transpose-load)
    int lk4 = (tid & 3) * 4;
    int lk  = tid >> 5;        // 0..7   (B direct load)
    int lm4 = (tid & 31) * 4;

    float acc[TM][TN] = {};

    for (int k0 = 0; k0 < Cq; k0 += BKT) {
        #pragma unroll
        for (int p = 0; p < 2; ++p) {
            int m = lr + p * 64;
            float4 v = *(const float4*)(Ag + (size_t)(m0 + m) * Cq + k0 + lk4);
            As[lk4 + 0][m] = v.x; As[lk4 + 1][m] = v.y;
            As[lk4 + 2][m] = v.z; As[lk4 + 3][m] = v.w;
        }
        #pragma unroll
        for (int p = 0; p < 2; ++p) {
            int k = lk + p * 8;
            float4 u = *(const float4*)(Bg + (size_t)(k0 + k) * Tq + n0 + lm4);
            *(float4*)&Bs[k][lm4] = u;
        }
        __syncthreads();
        #pragma unroll
        for (int kk = 0; kk < BKT; ++kk) {
            float a[TM], bb[TN];
            #pragma unroll
            for (int i = 0; i < TM; ++i) a[i]  = As[kk][ty * TM + i];
            #pragma unroll
            for (int j = 0; j < TN; ++j) bb[j] = Bs[kk][tx * TN + j];
            #pragma unroll
            for (int i = 0; i < TM; ++i)
                #pragma unroll
                for (int j = 0; j < TN; ++j)
                    acc[i][j] = fmaf(a[i], bb[j], acc[i][j]);
        }
        __syncthreads();
    }
    // out[b][n][m] = acc + b2[m] + x[b][n][m]   (m contiguous)
    float bias[TM];
    #pragma unroll
    for (int i = 0; i < TM; ++i) bias[i] = b2[m0 + ty * TM + i];
    #pragma unroll
    for (int j = 0; j < TN; ++j) {
        int n = n0 + tx * TN + j;
        size_t base = (size_t)b * Tq * Dq + (size_t)n * Dq + m0 + ty * TM;
        #pragma unroll
        for (int i = 0; i < TM; ++i)
            out[base + i] = acc[i][j] + bias[i] + x[base + i];
    }
}

// ---------------------------------------------------------------------------
extern "C" void kernel_launch(void* const* d_in, const int* in_sizes, int n_in,
                              void* d_out, int out_size) {
    const float* x   = (const float*)d_in[0];
    const float* d_w = (const float*)d_in[1];
    const float* d_g = (const float*)d_in[2];
    const float* d_b = (const float*)d_in[3];
    const float* p_w = (const float*)d_in[4];
    const float* p_g = (const float*)d_in[5];
    const float* p_b = (const float*)d_in[6];
    const float* w1  = (const float*)d_in[7];
    const float* b1  = (const float*)d_in[8];
    const float* w2  = (const float*)d_in[9];
    const float* b2  = (const float*)d_in[10];
    float* out = (float*)d_out;

    dnorm_kernel<<<Bq * Kq, 256>>>(d_w);
    pnorm_kernel<<<dim3(Bq, Cq / 256), 256>>>(p_w);
    gemm1_kernel<<<dim3(Tq / BN, Cq / BM, Bq), 256>>>(x, w1, b1);
    conv_kernel<<<Bq * Cq, 256>>>(d_w, d_g, d_b);
    gemm2_kernel<<<dim3(Tq / BN, Cq / BM, Bq), 256>>>(p_w, p_g, p_b);
    gemm3_kernel<<<dim3(Tq / BN, Dq / BM, Bq), 256>>>(x, w2, b2, out);
}